// round 1
// baseline (speedup 1.0000x reference)
#include <cuda_runtime.h>
#include <math.h>

#define BATCH 4
#define SEQ   4096
#define DIM   256
#define ROWS  (BATCH*SEQ)          // 16384
#define SCALE 0.0625f              // 1/sqrt(256)

// ---------------- scratch (static device globals; no runtime allocation) ----
__device__ float g_qp[(size_t)ROWS * DIM];
__device__ float g_kp[(size_t)ROWS * DIM];
__device__ float g_vp[(size_t)ROWS * DIM];
__device__ float g_ctx[(size_t)ROWS * DIM];
__device__ float g_m[ROWS];
__device__ float g_l[ROWS];

// ---------------------------------------------------------------------------
// Generic C[M,N] = A[M,K] @ W[K,N] + bias  (64x64 tile, BK=16, 256 threads,
// 4x4 per-thread microtile)
// ---------------------------------------------------------------------------
__global__ void gemm_bias_kernel(const float* __restrict__ A,
                                 const float* __restrict__ W,
                                 const float* __restrict__ bias,
                                 float* __restrict__ C,
                                 int M, int N, int K) {
    __shared__ float As[16][64];
    __shared__ float Bs[16][64];
    const int tid = threadIdx.x;
    const int tm  = (tid >> 4) << 2;
    const int tn  = (tid & 15) << 2;
    const int m0  = blockIdx.y * 64;
    const int n0  = blockIdx.x * 64;

    float acc[4][4] = {};
    for (int k0 = 0; k0 < K; k0 += 16) {
        #pragma unroll
        for (int i = 0; i < 4; i++) {
            int idx = tid + i * 256;
            int r  = idx >> 4, kk = idx & 15;
            As[kk][r] = A[(size_t)(m0 + r) * K + (k0 + kk)];
            int kr = idx >> 6, nn = idx & 63;
            Bs[kr][nn] = W[(size_t)(k0 + kr) * N + (n0 + nn)];
        }
        __syncthreads();
        #pragma unroll
        for (int kk = 0; kk < 16; kk++) {
            float a[4], b[4];
            #pragma unroll
            for (int i = 0; i < 4; i++) a[i] = As[kk][tm + i];
            #pragma unroll
            for (int j = 0; j < 4; j++) b[j] = Bs[kk][tn + j];
            #pragma unroll
            for (int i = 0; i < 4; i++)
                #pragma unroll
                for (int j = 0; j < 4; j++)
                    acc[i][j] += a[i] * b[j];
        }
        __syncthreads();
    }
    float4 bv4 = *(const float4*)&bias[n0 + tn];
    #pragma unroll
    for (int i = 0; i < 4; i++) {
        float4 out;
        out.x = acc[i][0] + bv4.x;
        out.y = acc[i][1] + bv4.y;
        out.z = acc[i][2] + bv4.z;
        out.w = acc[i][3] + bv4.w;
        *(float4*)&C[(size_t)(m0 + tm + i) * N + (n0 + tn)] = out;
    }
}

// ---------------------------------------------------------------------------
// logits[b, q, k] = (qp[b,q,:] . kp[b,k,:]) * SCALE, lower-triangular tiles only
// ---------------------------------------------------------------------------
__global__ void qk_kernel(float* __restrict__ logits) {
    const int bt = blockIdx.z;
    const int bm = blockIdx.y;   // query tile
    const int bn = blockIdx.x;   // key tile
    if (bn > bm) return;         // fully masked tile: never read downstream

    __shared__ float As[16][64];
    __shared__ float Bs[16][64];
    const int tid = threadIdx.x;
    const int tm  = (tid >> 4) << 2;
    const int tn  = (tid & 15) << 2;

    const float* A  = g_qp + ((size_t)bt * SEQ + bm * 64) * DIM;
    const float* Bm = g_kp + ((size_t)bt * SEQ + bn * 64) * DIM;

    float acc[4][4] = {};
    for (int k0 = 0; k0 < DIM; k0 += 16) {
        #pragma unroll
        for (int i = 0; i < 4; i++) {
            int idx = tid + i * 256;
            int r = idx >> 4, kk = idx & 15;
            As[kk][r] = A[(size_t)r * DIM + (k0 + kk)];
            Bs[kk][r] = Bm[(size_t)r * DIM + (k0 + kk)];
        }
        __syncthreads();
        #pragma unroll
        for (int kk = 0; kk < 16; kk++) {
            float a[4], b[4];
            #pragma unroll
            for (int i = 0; i < 4; i++) a[i] = As[kk][tm + i];
            #pragma unroll
            for (int j = 0; j < 4; j++) b[j] = Bs[kk][tn + j];
            #pragma unroll
            for (int i = 0; i < 4; i++)
                #pragma unroll
                for (int j = 0; j < 4; j++)
                    acc[i][j] += a[i] * b[j];
        }
        __syncthreads();
    }
    float* C = logits + ((size_t)bt * SEQ + bm * 64 + tm) * SEQ + bn * 64 + tn;
    #pragma unroll
    for (int i = 0; i < 4; i++) {
        float4 out;
        out.x = acc[i][0] * SCALE;
        out.y = acc[i][1] * SCALE;
        out.z = acc[i][2] * SCALE;
        out.w = acc[i][3] * SCALE;
        *(float4*)&C[(size_t)i * SEQ] = out;
    }
}

// ---------------------------------------------------------------------------
// Per-row online (max, sum-exp) over the causal prefix [0, r]
// ---------------------------------------------------------------------------
__global__ void rowstats_kernel(const float* __restrict__ logits) {
    const int b = blockIdx.y;
    const int r = blockIdx.x;
    const float* row = logits + ((size_t)b * SEQ + r) * SEQ;
    const int tid = threadIdx.x;

    float m = -1e30f, l = 0.f;
    for (int c = tid; c <= r; c += 256) {
        float x = row[c];
        if (x > m) { l = l * __expf(m - x) + 1.f; m = x; }
        else       { l += __expf(x - m); }
    }
    __shared__ float sm[256], sl[256];
    sm[tid] = m; sl[tid] = l;
    __syncthreads();
    for (int s = 128; s > 0; s >>= 1) {
        if (tid < s) {
            float m2 = sm[tid + s], l2 = sl[tid + s];
            float M = fmaxf(sm[tid], m2);
            sl[tid] = sl[tid] * __expf(sm[tid] - M) + l2 * __expf(m2 - M);
            sm[tid] = M;
        }
        __syncthreads();
    }
    if (tid == 0) {
        g_m[b * SEQ + r] = sm[0];
        g_l[b * SEQ + r] = sl[0];
    }
}

// ---------------------------------------------------------------------------
// attn = exp(logit - m) / l below/on diagonal, 0 above (in-place, float4)
// ---------------------------------------------------------------------------
__global__ void normalize_kernel(float* __restrict__ attn) {
    const int b = blockIdx.y;
    const int r = blockIdx.x;
    const float m   = g_m[b * SEQ + r];
    const float inv = 1.f / g_l[b * SEQ + r];
    float4* row = (float4*)(attn + ((size_t)b * SEQ + r) * SEQ);
    const int tid = threadIdx.x;
    for (int c4 = tid; c4 < SEQ / 4; c4 += 256) {
        int c = c4 * 4;
        float4 x = row[c4];
        float4 p;
        p.x = (c     <= r) ? __expf(x.x - m) * inv : 0.f;
        p.y = (c + 1 <= r) ? __expf(x.y - m) * inv : 0.f;
        p.z = (c + 2 <= r) ? __expf(x.z - m) * inv : 0.f;
        p.w = (c + 3 <= r) ? __expf(x.w - m) * inv : 0.f;
        row[c4] = p;
    }
}

// ---------------------------------------------------------------------------
// ctx[b,q,:] = attn[b,q,:] @ vp[b,:,:]  (k-loop truncated at diagonal tile)
// ---------------------------------------------------------------------------
__global__ void pv_kernel(const float* __restrict__ attn) {
    const int bt = blockIdx.z;
    const int bm = blockIdx.y;      // query tile
    const int bn = blockIdx.x;      // dim tile (DIM/64 = 4)
    __shared__ float As[16][64];
    __shared__ float Bs[16][64];
    const int tid = threadIdx.x;
    const int tm  = (tid >> 4) << 2;
    const int tn  = (tid & 15) << 2;

    const float* A = attn + ((size_t)bt * SEQ + bm * 64) * SEQ;
    const float* V = g_vp + (size_t)bt * SEQ * DIM;
    const int kmax = (bm + 1) * 64;  // attn is exactly 0 beyond row index

    float acc[4][4] = {};
    for (int k0 = 0; k0 < kmax; k0 += 16) {
        #pragma unroll
        for (int i = 0; i < 4; i++) {
            int idx = tid + i * 256;
            int r = idx >> 4, kk = idx & 15;
            As[kk][r] = A[(size_t)r * SEQ + (k0 + kk)];
            int kr = idx >> 6, nn = idx & 63;
            Bs[kr][nn] = V[(size_t)(k0 + kr) * DIM + bn * 64 + nn];
        }
        __syncthreads();
        #pragma unroll
        for (int kk = 0; kk < 16; kk++) {
            float a[4], b[4];
            #pragma unroll
            for (int i = 0; i < 4; i++) a[i] = As[kk][tm + i];
            #pragma unroll
            for (int j = 0; j < 4; j++) b[j] = Bs[kk][tn + j];
            #pragma unroll
            for (int i = 0; i < 4; i++)
                #pragma unroll
                for (int j = 0; j < 4; j++)
                    acc[i][j] += a[i] * b[j];
        }
        __syncthreads();
    }
    float* C = g_ctx + ((size_t)bt * SEQ + bm * 64 + tm) * DIM + bn * 64 + tn;
    #pragma unroll
    for (int i = 0; i < 4; i++) {
        float4 out;
        out.x = acc[i][0]; out.y = acc[i][1]; out.z = acc[i][2]; out.w = acc[i][3];
        *(float4*)&C[(size_t)i * DIM] = out;
    }
}

// ---------------------------------------------------------------------------
extern "C" void kernel_launch(void* const* d_in, const int* in_sizes, int n_in,
                              void* d_out, int out_size) {
    const float* q  = (const float*)d_in[0];
    const float* k  = (const float*)d_in[1];
    const float* v  = (const float*)d_in[2];
    // d_in[3] = mask: known causal (triu k=1); handled analytically
    const float* Wq = (const float*)d_in[4];
    const float* bq = (const float*)d_in[5];
    const float* Wk = (const float*)d_in[6];
    const float* bk = (const float*)d_in[7];
    const float* Wv = (const float*)d_in[8];
    const float* bv = (const float*)d_in[9];
    const float* Wo = (const float*)d_in[10];
    const float* bo = (const float*)d_in[11];

    float* z    = (float*)d_out;                       // [B,S,D]
    float* attn = z + (size_t)BATCH * SEQ * DIM;       // [B,S,S]

    float *qp, *kp, *vp, *ctx;
    cudaGetSymbolAddress((void**)&qp,  g_qp);
    cudaGetSymbolAddress((void**)&kp,  g_kp);
    cudaGetSymbolAddress((void**)&vp,  g_vp);
    cudaGetSymbolAddress((void**)&ctx, g_ctx);

    dim3 tb(256);
    dim3 gproj(DIM / 64, ROWS / 64);

    gemm_bias_kernel<<<gproj, tb>>>(q, Wq, bq, qp, ROWS, DIM, DIM);
    gemm_bias_kernel<<<gproj, tb>>>(k, Wk, bk, kp, ROWS, DIM, DIM);
    gemm_bias_kernel<<<gproj, tb>>>(v, Wv, bv, vp, ROWS, DIM, DIM);

    qk_kernel<<<dim3(SEQ / 64, SEQ / 64, BATCH), tb>>>(attn);
    rowstats_kernel<<<dim3(SEQ, BATCH), tb>>>(attn);
    normalize_kernel<<<dim3(SEQ, BATCH), tb>>>(attn);
    pv_kernel<<<dim3(DIM / 64, SEQ / 64, BATCH), tb>>>(attn);

    gemm_bias_kernel<<<gproj, tb>>>(ctx, Wo, bo, z, ROWS, DIM, DIM);
}

// round 3
// speedup vs baseline: 1.7542x; 1.7542x over previous
#include <cuda_runtime.h>
#include <math.h>

#define BATCH 4
#define SEQ   4096
#define DIM   256
#define ROWS  (BATCH*SEQ)          // 16384
#define SCALE 0.0625f              // 1/sqrt(256)

#define BM 128
#define BN 128
#define BK 8
#define PAD 4

// ---------------- scratch (static device globals; no runtime allocation) ----
__device__ float g_qp[(size_t)ROWS * DIM];
__device__ float g_kp[(size_t)ROWS * DIM];
__device__ float g_vp[(size_t)ROWS * DIM];
__device__ float g_ctx[(size_t)ROWS * DIM];

// ===========================================================================
// C[M,N] = A[M,K] @ W[K,N] + bias   (128x128x8 tile, 256 thr, 8x8 microtile,
// double-buffered smem, register prefetch)
// ===========================================================================
__global__ __launch_bounds__(256, 2)
void gemm_bias_kernel(const float* __restrict__ A,
                      const float* __restrict__ W,
                      const float* __restrict__ bias,
                      float* __restrict__ C,
                      int M, int N, int K) {
    __shared__ float As[2][BK][BM + PAD];
    __shared__ float Bs[2][BK][BN];

    const int tid = threadIdx.x;
    const int tx  = tid & 15;      // 0..15  (col group)
    const int ty  = tid >> 4;      // 0..15  (row group)
    const int m0  = blockIdx.y * BM;
    const int n0  = blockIdx.x * BN;

    const int aRow = tid >> 1;            // 0..127
    const int aCol = (tid & 1) * 4;       // 0 or 4
    const int bRow = tid >> 5;            // 0..7
    const int bCol = (tid & 31) * 4;      // 0..124

    const float* Aptr = A + (size_t)(m0 + aRow) * K + aCol;
    const float* Bptr = W + (size_t)bRow * N + n0 + bCol;

    float4 ar = *(const float4*)Aptr;
    float4 br = *(const float4*)Bptr;

    As[0][aCol + 0][aRow] = ar.x;
    As[0][aCol + 1][aRow] = ar.y;
    As[0][aCol + 2][aRow] = ar.z;
    As[0][aCol + 3][aRow] = ar.w;
    *(float4*)&Bs[0][bRow][bCol] = br;
    __syncthreads();

    float acc[8][8] = {};
    const int T = K / BK;

    for (int t = 0; t < T; t++) {
        const int cur = t & 1;
        if (t + 1 < T) {
            ar = *(const float4*)(Aptr + (t + 1) * BK);
            br = *(const float4*)(Bptr + (size_t)(t + 1) * BK * N);
        }
        #pragma unroll
        for (int kk = 0; kk < BK; kk++) {
            float a[8], b[8];
            *(float4*)&a[0] = *(const float4*)&As[cur][kk][ty * 4];
            *(float4*)&a[4] = *(const float4*)&As[cur][kk][ty * 4 + 64];
            *(float4*)&b[0] = *(const float4*)&Bs[cur][kk][tx * 4];
            *(float4*)&b[4] = *(const float4*)&Bs[cur][kk][tx * 4 + 64];
            #pragma unroll
            for (int i = 0; i < 8; i++)
                #pragma unroll
                for (int j = 0; j < 8; j++)
                    acc[i][j] += a[i] * b[j];
        }
        if (t + 1 < T) {
            const int nxt = cur ^ 1;
            As[nxt][aCol + 0][aRow] = ar.x;
            As[nxt][aCol + 1][aRow] = ar.y;
            As[nxt][aCol + 2][aRow] = ar.z;
            As[nxt][aCol + 3][aRow] = ar.w;
            *(float4*)&Bs[nxt][bRow][bCol] = br;
            __syncthreads();
        }
    }

    #pragma unroll
    for (int ih = 0; ih < 2; ih++)
        #pragma unroll
        for (int i = 0; i < 4; i++) {
            const int m = m0 + ih * 64 + ty * 4 + i;
            #pragma unroll
            for (int jh = 0; jh < 2; jh++) {
                const int n = n0 + jh * 64 + tx * 4;
                float4 bv4 = *(const float4*)&bias[n];
                float4 o;
                o.x = acc[ih * 4 + i][jh * 4 + 0] + bv4.x;
                o.y = acc[ih * 4 + i][jh * 4 + 1] + bv4.y;
                o.z = acc[ih * 4 + i][jh * 4 + 2] + bv4.z;
                o.w = acc[ih * 4 + i][jh * 4 + 3] + bv4.w;
                *(float4*)&C[(size_t)m * N + n] = o;
            }
        }
}

// ===========================================================================
// logits[b,q,k] = (qp . kp) * SCALE, lower-triangular 128x128 tiles only.
// Both operands K-major (transposed loads).
// ===========================================================================
__global__ __launch_bounds__(256, 2)
void qk_kernel(float* __restrict__ logits) {
    const int bt = blockIdx.z;
    const int bm = blockIdx.y;
    const int bn = blockIdx.x;
    if (bn > bm) return;

    __shared__ float As[2][BK][BM + PAD];
    __shared__ float Bs[2][BK][BN + PAD];

    const int tid = threadIdx.x;
    const int tx  = tid & 15;
    const int ty  = tid >> 4;

    const int aRow = tid >> 1;
    const int aCol = (tid & 1) * 4;

    const float* Aptr = g_qp + ((size_t)bt * SEQ + bm * BM + aRow) * DIM + aCol;
    const float* Bptr = g_kp + ((size_t)bt * SEQ + bn * BN + aRow) * DIM + aCol;

    float4 ar = *(const float4*)Aptr;
    float4 br = *(const float4*)Bptr;

    As[0][aCol + 0][aRow] = ar.x;
    As[0][aCol + 1][aRow] = ar.y;
    As[0][aCol + 2][aRow] = ar.z;
    As[0][aCol + 3][aRow] = ar.w;
    Bs[0][aCol + 0][aRow] = br.x;
    Bs[0][aCol + 1][aRow] = br.y;
    Bs[0][aCol + 2][aRow] = br.z;
    Bs[0][aCol + 3][aRow] = br.w;
    __syncthreads();

    float acc[8][8] = {};
    const int T = DIM / BK;   // 32

    for (int t = 0; t < T; t++) {
        const int cur = t & 1;
        if (t + 1 < T) {
            ar = *(const float4*)(Aptr + (t + 1) * BK);
            br = *(const float4*)(Bptr + (t + 1) * BK);
        }
        #pragma unroll
        for (int kk = 0; kk < BK; kk++) {
            float a[8], b[8];
            *(float4*)&a[0] = *(const float4*)&As[cur][kk][ty * 4];
            *(float4*)&a[4] = *(const float4*)&As[cur][kk][ty * 4 + 64];
            *(float4*)&b[0] = *(const float4*)&Bs[cur][kk][tx * 4];
            *(float4*)&b[4] = *(const float4*)&Bs[cur][kk][tx * 4 + 64];
            #pragma unroll
            for (int i = 0; i < 8; i++)
                #pragma unroll
                for (int j = 0; j < 8; j++)
                    acc[i][j] += a[i] * b[j];
        }
        if (t + 1 < T) {
            const int nxt = cur ^ 1;
            As[nxt][aCol + 0][aRow] = ar.x;
            As[nxt][aCol + 1][aRow] = ar.y;
            As[nxt][aCol + 2][aRow] = ar.z;
            As[nxt][aCol + 3][aRow] = ar.w;
            Bs[nxt][aCol + 0][aRow] = br.x;
            Bs[nxt][aCol + 1][aRow] = br.y;
            Bs[nxt][aCol + 2][aRow] = br.z;
            Bs[nxt][aCol + 3][aRow] = br.w;
            __syncthreads();
        }
    }

    float* Cb = logits + ((size_t)bt * SEQ + bm * BM) * SEQ + bn * BN;
    #pragma unroll
    for (int ih = 0; ih < 2; ih++)
        #pragma unroll
        for (int i = 0; i < 4; i++) {
            const int m = ih * 64 + ty * 4 + i;
            #pragma unroll
            for (int jh = 0; jh < 2; jh++) {
                const int n = jh * 64 + tx * 4;
                float4 o;
                o.x = acc[ih * 4 + i][jh * 4 + 0] * SCALE;
                o.y = acc[ih * 4 + i][jh * 4 + 1] * SCALE;
                o.z = acc[ih * 4 + i][jh * 4 + 2] * SCALE;
                o.w = acc[ih * 4 + i][jh * 4 + 3] * SCALE;
                *(float4*)&Cb[(size_t)m * SEQ + n] = o;
            }
        }
}

// ===========================================================================
// Fused causal softmax (in-place): one block per row, row cached in smem.
// ===========================================================================
__global__ void softmax_kernel(float* __restrict__ attn) {
    const int b = blockIdx.y;
    const int r = blockIdx.x;
    float* row = attn + ((size_t)b * SEQ + r) * SEQ;
    const int tid = threadIdx.x;

    __shared__ float buf[SEQ];
    __shared__ float sm[256], sl[256];

    float m = -1e30f, l = 0.f;
    for (int c = tid; c <= r; c += 256) {
        float x = row[c];
        buf[c] = x;
        if (x > m) { l = l * __expf(m - x) + 1.f; m = x; }
        else       { l += __expf(x - m); }
    }
    sm[tid] = m; sl[tid] = l;
    __syncthreads();
    for (int s = 128; s > 0; s >>= 1) {
        if (tid < s) {
            float m2 = sm[tid + s], l2 = sl[tid + s];
            float M = fmaxf(sm[tid], m2);
            sl[tid] = sl[tid] * __expf(sm[tid] - M) + l2 * __expf(m2 - M);
            sm[tid] = M;
        }
        __syncthreads();
    }
    const float M   = sm[0];
    const float inv = 1.f / sl[0];

    for (int c = tid; c <= r; c += 256)
        row[c] = __expf(buf[c] - M) * inv;
    for (int c = r + 1 + tid; c < SEQ; c += 256)
        row[c] = 0.f;
}

// ===========================================================================
// ctx = attn @ vp  (k-loop truncated at the diagonal tile; attn==0 beyond)
// ===========================================================================
__global__ __launch_bounds__(256, 2)
void pv_kernel(const float* __restrict__ attn) {
    const int bt = blockIdx.z;
    const int bm = blockIdx.y;     // query tile (SEQ/128)
    const int bn = blockIdx.x;     // dim tile  (DIM/128 = 2)

    __shared__ float As[2][BK][BM + PAD];
    __shared__ float Bs[2][BK][BN];

    const int tid = threadIdx.x;
    const int tx  = tid & 15;
    const int ty  = tid >> 4;

    const int aRow = tid >> 1;
    const int aCol = (tid & 1) * 4;
    const int bRow = tid >> 5;
    const int bCol = (tid & 31) * 4;

    const float* Aptr = attn + ((size_t)bt * SEQ + bm * BM + aRow) * SEQ + aCol;
    const float* Bptr = g_vp + ((size_t)bt * SEQ + bRow) * DIM + bn * BN + bCol;

    float4 ar = *(const float4*)Aptr;
    float4 br = *(const float4*)Bptr;

    As[0][aCol + 0][aRow] = ar.x;
    As[0][aCol + 1][aRow] = ar.y;
    As[0][aCol + 2][aRow] = ar.z;
    As[0][aCol + 3][aRow] = ar.w;
    *(float4*)&Bs[0][bRow][bCol] = br;
    __syncthreads();

    float acc[8][8] = {};
    const int T = (bm + 1) * BM / BK;   // truncated k-range

    for (int t = 0; t < T; t++) {
        const int cur = t & 1;
        if (t + 1 < T) {
            ar = *(const float4*)(Aptr + (t + 1) * BK);
            br = *(const float4*)(Bptr + (size_t)(t + 1) * BK * DIM);
        }
        #pragma unroll
        for (int kk = 0; kk < BK; kk++) {
            float a[8], b[8];
            *(float4*)&a[0] = *(const float4*)&As[cur][kk][ty * 4];
            *(float4*)&a[4] = *(const float4*)&As[cur][kk][ty * 4 + 64];
            *(float4*)&b[0] = *(const float4*)&Bs[cur][kk][tx * 4];
            *(float4*)&b[4] = *(const float4*)&Bs[cur][kk][tx * 4 + 64];
            #pragma unroll
            for (int i = 0; i < 8; i++)
                #pragma unroll
                for (int j = 0; j < 8; j++)
                    acc[i][j] += a[i] * b[j];
        }
        if (t + 1 < T) {
            const int nxt = cur ^ 1;
            As[nxt][aCol + 0][aRow] = ar.x;
            As[nxt][aCol + 1][aRow] = ar.y;
            As[nxt][aCol + 2][aRow] = ar.z;
            As[nxt][aCol + 3][aRow] = ar.w;
            *(float4*)&Bs[nxt][bRow][bCol] = br;
            __syncthreads();
        }
    }

    float* Cb = g_ctx + ((size_t)bt * SEQ + bm * BM) * DIM + bn * BN;
    #pragma unroll
    for (int ih = 0; ih < 2; ih++)
        #pragma unroll
        for (int i = 0; i < 4; i++) {
            const int m = ih * 64 + ty * 4 + i;
            #pragma unroll
            for (int jh = 0; jh < 2; jh++) {
                const int n = jh * 64 + tx * 4;
                float4 o;
                o.x = acc[ih * 4 + i][jh * 4 + 0];
                o.y = acc[ih * 4 + i][jh * 4 + 1];
                o.z = acc[ih * 4 + i][jh * 4 + 2];
                o.w = acc[ih * 4 + i][jh * 4 + 3];
                *(float4*)&Cb[(size_t)m * DIM + n] = o;
            }
        }
}

// ===========================================================================
extern "C" void kernel_launch(void* const* d_in, const int* in_sizes, int n_in,
                              void* d_out, int out_size) {
    const float* q  = (const float*)d_in[0];
    const float* k  = (const float*)d_in[1];
    const float* v  = (const float*)d_in[2];
    // d_in[3] = mask: known causal (triu k=1); handled analytically
    const float* Wq = (const float*)d_in[4];
    const float* bq = (const float*)d_in[5];
    const float* Wk = (const float*)d_in[6];
    const float* bk = (const float*)d_in[7];
    const float* Wv = (const float*)d_in[8];
    const float* bv = (const float*)d_in[9];
    const float* Wo = (const float*)d_in[10];
    const float* bo = (const float*)d_in[11];

    float* z    = (float*)d_out;                       // [B,S,D]
    float* attn = z + (size_t)BATCH * SEQ * DIM;       // [B,S,S]

    float *qp, *kp, *vp, *ctx;
    cudaGetSymbolAddress((void**)&qp,  g_qp);
    cudaGetSymbolAddress((void**)&kp,  g_kp);
    cudaGetSymbolAddress((void**)&vp,  g_vp);
    cudaGetSymbolAddress((void**)&ctx, g_ctx);

    dim3 tb(256);
    dim3 gproj(DIM / BN, ROWS / BM);                   // (2, 128)

    gemm_bias_kernel<<<gproj, tb>>>(q, Wq, bq, qp, ROWS, DIM, DIM);
    gemm_bias_kernel<<<gproj, tb>>>(k, Wk, bk, kp, ROWS, DIM, DIM);
    gemm_bias_kernel<<<gproj, tb>>>(v, Wv, bv, vp, ROWS, DIM, DIM);

    qk_kernel<<<dim3(SEQ / BN, SEQ / BM, BATCH), tb>>>(attn);
    softmax_kernel<<<dim3(SEQ, BATCH), tb>>>(attn);
    pv_kernel<<<dim3(DIM / BN, SEQ / BM, BATCH), tb>>>(attn);

    gemm_bias_kernel<<<gproj, tb>>>(ctx, Wo, bo, z, ROWS, DIM, DIM);
}